// round 1
// baseline (speedup 1.0000x reference)
#include <cuda_runtime.h>
#include <cstdint>

#define NN 100000
#define NE 800000
#define H  64
#define EPB 64
#define NT 256
#define RP 132
#define SMEM_BYTES ((8192 + 64 + 128 + EPB * RP) * 4)

// Scratch (device globals: allocation-free rule)
__device__ __align__(16) float g_x[(size_t)NN * H];
__device__ __align__(16) float g_agg[(size_t)NN * H];
__device__ float g_cnt[NN];
__device__ float g_sum[H];
__device__ unsigned g_maxb[H];

// ---------- packed f32x2 helpers (full-rate fp32 on sm_103a) ----------
__device__ __forceinline__ uint64_t pk2(float lo, float hi) {
    uint64_t r;
    asm("mov.b64 %0, {%1, %2};" : "=l"(r) : "r"(__float_as_uint(lo)), "r"(__float_as_uint(hi)));
    return r;
}
__device__ __forceinline__ uint64_t dup2(float a) {
    uint64_t r;
    asm("mov.b64 %0, {%1, %1};" : "=l"(r) : "r"(__float_as_uint(a)));
    return r;
}
__device__ __forceinline__ void fma2(uint64_t& acc, uint64_t w, uint64_t p) {
    asm("fma.rn.f32x2 %0, %1, %2, %0;" : "+l"(acc) : "l"(w), "l"(p));
}
__device__ __forceinline__ void unpk(uint64_t v, float& lo, float& hi) {
    unsigned a, b;
    asm("mov.b64 {%0, %1}, %2;" : "=r"(a), "=r"(b) : "l"(v));
    lo = __uint_as_float(a); hi = __uint_as_float(b);
}
__device__ __forceinline__ void redv4(float* p, float a, float b, float c, float d) {
    asm volatile("red.global.add.v4.f32 [%0], {%1, %2, %3, %4};"
                 :: "l"(p), "f"(a), "f"(b), "f"(c), "f"(d) : "memory");
}
__device__ __forceinline__ unsigned encf(float f) {
    unsigned u = __float_as_uint(f);
    return (u & 0x80000000u) ? ~u : (u | 0x80000000u);
}
__device__ __forceinline__ float decf(unsigned u) {
    return (u & 0x80000000u) ? __uint_as_float(u & 0x7FFFFFFFu) : __uint_as_float(~u);
}

// ---------- small kernels ----------
__global__ void k_init() {
    int i = blockIdx.x * blockDim.x + threadIdx.x;
    int stride = gridDim.x * blockDim.x;
    for (int n = i; n < NN; n += stride) g_cnt[n] = 0.f;
    if (i < H) { g_sum[i] = 0.f; g_maxb[i] = 0u; }
}

__global__ void k_count(const int* __restrict__ edges) {
    int i = blockIdx.x * blockDim.x + threadIdx.x;
    int stride = gridDim.x * blockDim.x;
    for (int e = i; e < NE; e += stride)
        atomicAdd(&g_cnt[edges[2 * e + 1]], 1.0f);
}

__global__ void k_embed(const int* __restrict__ ti, const float* __restrict__ et) {
    int i = blockIdx.x * blockDim.x + threadIdx.x;
    int stride = gridDim.x * blockDim.x;
    for (int lin = i; lin < NN * 16; lin += stride) {
        int n = lin >> 4, q = lin & 15;
        ((float4*)g_x)[lin] = ((const float4*)et)[ti[n] * 16 + q];
    }
}

__global__ void k_zero_agg() {
    int i = blockIdx.x * blockDim.x + threadIdx.x;
    int stride = gridDim.x * blockDim.x;
    float4 z = make_float4(0.f, 0.f, 0.f, 0.f);
    for (int lin = i; lin < NN * 16; lin += stride)
        ((float4*)g_agg)[lin] = z;
}

// ---------- edge message GEMM + aggregation ----------
// msg = relu([x[src]; x[tgt]] @ W + b); red.v4 into g_agg[tgt]
__global__ __launch_bounds__(NT, 3) void k_edge(const int* __restrict__ edges,
                                                const float* __restrict__ W,
                                                const float* __restrict__ B) {
    extern __shared__ float sm[];
    float* Wsh  = sm;
    float* bsh  = sm + 8192;
    float* insh = sm + 8192 + 64 + 128;

    const int tid = threadIdx.x;
    for (int i = tid; i < 2048; i += NT) ((float4*)Wsh)[i] = ((const float4*)W)[i];
    if (tid < 16) ((float4*)bsh)[tid] = ((const float4*)B)[tid];
    __syncthreads();

    const int eg = tid >> 3, tg = tid & 7, j0 = tg << 3;
    const float* r0 = insh + eg * RP;
    const float* r1 = insh + (eg + 32) * RP;
    const float* wp = Wsh + j0;

    const int ntiles = NE / EPB;  // 12500 exact
    for (int tile = blockIdx.x; tile < ntiles; tile += gridDim.x) {
        const int base = tile * EPB;
        #pragma unroll
        for (int r = 0; r < 8; r++) {
            int lin = r * NT + tid;
            int e = lin >> 5, q = lin & 31;
            int node = edges[(base + e) * 2 + (q >> 4)];
            ((float4*)(insh + e * RP))[q] = ((const float4*)g_x)[node * 16 + (q & 15)];
        }
        __syncthreads();

        uint64_t a00 = pk2(bsh[j0+0], bsh[j0+1]);
        uint64_t a01 = pk2(bsh[j0+2], bsh[j0+3]);
        uint64_t a02 = pk2(bsh[j0+4], bsh[j0+5]);
        uint64_t a03 = pk2(bsh[j0+6], bsh[j0+7]);
        uint64_t a10 = a00, a11 = a01, a12 = a02, a13 = a03;

        #pragma unroll 16
        for (int k = 0; k < 128; k++) {
            uint64_t p0 = dup2(r0[k]);
            uint64_t p1 = dup2(r1[k]);
            const ulonglong2* w = (const ulonglong2*)(wp + k * 64);
            ulonglong2 wa = w[0];
            ulonglong2 wb = w[1];
            fma2(a00, wa.x, p0); fma2(a01, wa.y, p0);
            fma2(a02, wb.x, p0); fma2(a03, wb.y, p0);
            fma2(a10, wa.x, p1); fma2(a11, wa.y, p1);
            fma2(a12, wb.x, p1); fma2(a13, wb.y, p1);
        }

        {
            int t = edges[(base + eg) * 2 + 1];
            float v0,v1,v2,v3,v4,v5,v6,v7;
            unpk(a00,v0,v1); unpk(a01,v2,v3); unpk(a02,v4,v5); unpk(a03,v6,v7);
            float* dst = g_agg + (size_t)t * H + j0;
            redv4(dst,   fmaxf(v0,0.f), fmaxf(v1,0.f), fmaxf(v2,0.f), fmaxf(v3,0.f));
            redv4(dst+4, fmaxf(v4,0.f), fmaxf(v5,0.f), fmaxf(v6,0.f), fmaxf(v7,0.f));
        }
        {
            int t = edges[(base + eg + 32) * 2 + 1];
            float v0,v1,v2,v3,v4,v5,v6,v7;
            unpk(a10,v0,v1); unpk(a11,v2,v3); unpk(a12,v4,v5); unpk(a13,v6,v7);
            float* dst = g_agg + (size_t)t * H + j0;
            redv4(dst,   fmaxf(v0,0.f), fmaxf(v1,0.f), fmaxf(v2,0.f), fmaxf(v3,0.f));
            redv4(dst+4, fmaxf(v4,0.f), fmaxf(v5,0.f), fmaxf(v6,0.f), fmaxf(v7,0.f));
        }
        __syncthreads();
    }
}

// ---------- node update GEMM + residual + LayerNorm ----------
// u = relu([x[n]; agg[n]/cnt[n]] @ W + b); x[n] = LN(u + x[n]) * g + b
__global__ __launch_bounds__(NT, 3) void k_upd(const float* __restrict__ W,
                                               const float* __restrict__ B,
                                               const float* __restrict__ lng,
                                               const float* __restrict__ lnb) {
    extern __shared__ float sm[];
    float* Wsh  = sm;
    float* bsh  = sm + 8192;
    float* gsh  = sm + 8192 + 64;
    float* b2sh = gsh + 64;
    float* insh = sm + 8192 + 64 + 128;

    const int tid = threadIdx.x;
    for (int i = tid; i < 2048; i += NT) ((float4*)Wsh)[i] = ((const float4*)W)[i];
    if (tid < 16) ((float4*)bsh)[tid] = ((const float4*)B)[tid];
    if (tid >= 32 && tid < 48) ((float4*)gsh)[tid - 32]  = ((const float4*)lng)[tid - 32];
    if (tid >= 64 && tid < 80) ((float4*)b2sh)[tid - 64] = ((const float4*)lnb)[tid - 64];
    __syncthreads();

    const int eg = tid >> 3, tg = tid & 7, j0 = tg << 3;
    const float* r0 = insh + eg * RP;
    const float* r1 = insh + (eg + 32) * RP;
    const float* wp = Wsh + j0;

    const int ntiles = (NN + EPB - 1) / EPB;
    for (int tile = blockIdx.x; tile < ntiles; tile += gridDim.x) {
        const int base = tile * EPB;
        #pragma unroll
        for (int r = 0; r < 8; r++) {
            int lin = r * NT + tid;
            int nl = lin >> 5, q = lin & 31;
            int gn = base + nl;
            if (gn < NN) {
                float4 v;
                if (q < 16) {
                    v = ((const float4*)g_x)[gn * 16 + q];
                } else {
                    v = ((const float4*)g_agg)[gn * 16 + (q - 16)];
                    float ic = 1.0f / fmaxf(g_cnt[gn], 1.0f);
                    v.x *= ic; v.y *= ic; v.z *= ic; v.w *= ic;
                }
                ((float4*)(insh + nl * RP))[q] = v;
            }
        }
        __syncthreads();

        uint64_t a00 = pk2(bsh[j0+0], bsh[j0+1]);
        uint64_t a01 = pk2(bsh[j0+2], bsh[j0+3]);
        uint64_t a02 = pk2(bsh[j0+4], bsh[j0+5]);
        uint64_t a03 = pk2(bsh[j0+6], bsh[j0+7]);
        uint64_t a10 = a00, a11 = a01, a12 = a02, a13 = a03;

        #pragma unroll 16
        for (int k = 0; k < 128; k++) {
            uint64_t p0 = dup2(r0[k]);
            uint64_t p1 = dup2(r1[k]);
            const ulonglong2* w = (const ulonglong2*)(wp + k * 64);
            ulonglong2 wa = w[0];
            ulonglong2 wb = w[1];
            fma2(a00, wa.x, p0); fma2(a01, wa.y, p0);
            fma2(a02, wb.x, p0); fma2(a03, wb.y, p0);
            fma2(a10, wa.x, p1); fma2(a11, wa.y, p1);
            fma2(a12, wb.x, p1); fma2(a13, wb.y, p1);
        }

        // node 0 epilogue (shuffles must be executed by all lanes — no early divergence)
        {
            float h[8];
            { float lo, hi;
              unpk(a00, lo, hi); h[0] = fmaxf(lo,0.f) + r0[j0+0]; h[1] = fmaxf(hi,0.f) + r0[j0+1];
              unpk(a01, lo, hi); h[2] = fmaxf(lo,0.f) + r0[j0+2]; h[3] = fmaxf(hi,0.f) + r0[j0+3];
              unpk(a02, lo, hi); h[4] = fmaxf(lo,0.f) + r0[j0+4]; h[5] = fmaxf(hi,0.f) + r0[j0+5];
              unpk(a03, lo, hi); h[6] = fmaxf(lo,0.f) + r0[j0+6]; h[7] = fmaxf(hi,0.f) + r0[j0+7]; }
            float s1 = 0.f, s2 = 0.f;
            #pragma unroll
            for (int i = 0; i < 8; i++) { s1 += h[i]; s2 += h[i] * h[i]; }
            #pragma unroll
            for (int d = 1; d < 8; d <<= 1) {
                s1 += __shfl_xor_sync(0xFFFFFFFFu, s1, d);
                s2 += __shfl_xor_sync(0xFFFFFFFFu, s2, d);
            }
            float mu  = s1 * 0.015625f;
            float var = s2 * 0.015625f - mu * mu;
            float sc  = rsqrtf(fmaxf(var, 0.f) + 1e-5f);
            int gn0 = base + eg;
            if (gn0 < NN) {
                float o[8];
                #pragma unroll
                for (int i = 0; i < 8; i++) o[i] = (h[i] - mu) * sc * gsh[j0+i] + b2sh[j0+i];
                float4* dst = (float4*)(g_x + (size_t)gn0 * H + j0);
                dst[0] = make_float4(o[0], o[1], o[2], o[3]);
                dst[1] = make_float4(o[4], o[5], o[6], o[7]);
            }
        }
        // node 1 epilogue
        {
            float h[8];
            { float lo, hi;
              unpk(a10, lo, hi); h[0] = fmaxf(lo,0.f) + r1[j0+0]; h[1] = fmaxf(hi,0.f) + r1[j0+1];
              unpk(a11, lo, hi); h[2] = fmaxf(lo,0.f) + r1[j0+2]; h[3] = fmaxf(hi,0.f) + r1[j0+3];
              unpk(a12, lo, hi); h[4] = fmaxf(lo,0.f) + r1[j0+4]; h[5] = fmaxf(hi,0.f) + r1[j0+5];
              unpk(a13, lo, hi); h[6] = fmaxf(lo,0.f) + r1[j0+6]; h[7] = fmaxf(hi,0.f) + r1[j0+7]; }
            float s1 = 0.f, s2 = 0.f;
            #pragma unroll
            for (int i = 0; i < 8; i++) { s1 += h[i]; s2 += h[i] * h[i]; }
            #pragma unroll
            for (int d = 1; d < 8; d <<= 1) {
                s1 += __shfl_xor_sync(0xFFFFFFFFu, s1, d);
                s2 += __shfl_xor_sync(0xFFFFFFFFu, s2, d);
            }
            float mu  = s1 * 0.015625f;
            float var = s2 * 0.015625f - mu * mu;
            float sc  = rsqrtf(fmaxf(var, 0.f) + 1e-5f);
            int gn1 = base + eg + 32;
            if (gn1 < NN) {
                float o[8];
                #pragma unroll
                for (int i = 0; i < 8; i++) o[i] = (h[i] - mu) * sc * gsh[j0+i] + b2sh[j0+i];
                float4* dst = (float4*)(g_x + (size_t)gn1 * H + j0);
                dst[0] = make_float4(o[0], o[1], o[2], o[3]);
                dst[1] = make_float4(o[4], o[5], o[6], o[7]);
            }
        }
        __syncthreads();
    }
}

// ---------- final mean/max over nodes ----------
__global__ void k_reduce() {
    __shared__ float rs[4][64];
    __shared__ float rm[4][64];
    int j = threadIdx.x & 63, g = threadIdx.x >> 6;
    float s = 0.f, m = -3.402823466e38f;
    for (int n = blockIdx.x * 4 + g; n < NN; n += gridDim.x * 4) {
        float v = g_x[(size_t)n * H + j];
        s += v; m = fmaxf(m, v);
    }
    rs[g][j] = s; rm[g][j] = m;
    __syncthreads();
    if (g == 0) {
        #pragma unroll
        for (int i = 1; i < 4; i++) { s += rs[i][j]; m = fmaxf(m, rm[i][j]); }
        atomicAdd(&g_sum[j], s);
        atomicMax(&g_maxb[j], encf(m));
    }
}

__global__ void k_final(float* out) {
    int t = threadIdx.x;
    if (t < 64) out[t] = g_sum[t] * (1.0f / NN);
    else        out[t] = decf(g_maxb[t - 64]);
}

// ---------- launch ----------
extern "C" void kernel_launch(void* const* d_in, const int* in_sizes, int n_in,
                              void* d_out, int out_size) {
    const int*   ti    = (const int*)d_in[0];
    const int*   edges = (const int*)d_in[1];
    const float* et    = (const float*)d_in[2];
    const float* msg_w = (const float*)d_in[3];
    const float* msg_b = (const float*)d_in[4];
    const float* upd_w = (const float*)d_in[5];
    const float* upd_b = (const float*)d_in[6];
    const float* lng   = (const float*)d_in[7];
    const float* lnb   = (const float*)d_in[8];
    float* out = (float*)d_out;

    cudaFuncSetAttribute(k_edge, cudaFuncAttributeMaxDynamicSharedMemorySize, SMEM_BYTES);
    cudaFuncSetAttribute(k_upd,  cudaFuncAttributeMaxDynamicSharedMemorySize, SMEM_BYTES);

    k_init<<<392, 256>>>();
    k_embed<<<512, 256>>>(ti, et);
    k_count<<<512, 256>>>(edges);

    for (int l = 0; l < 3; l++) {
        k_zero_agg<<<512, 256>>>();
        k_edge<<<456, NT, SMEM_BYTES>>>(edges, msg_w + l * 8192, msg_b + l * 64);
        k_upd<<<456, NT, SMEM_BYTES>>>(upd_w + l * 8192, upd_b + l * 64,
                                       lng + l * 64, lnb + l * 64);
    }

    k_reduce<<<296, 256>>>();
    k_final<<<1, 128>>>(out);
}

// round 2
// speedup vs baseline: 3.0148x; 3.0148x over previous
#include <cuda_runtime.h>
#include <cstdint>

#define NN 100000
#define NE 800000
#define H  64
#define EPB 64
#define NT 256
#define RP 132
#define PRP 68
#define SMEM_UPD ((8192 + 64 + 128 + EPB * RP) * 4)
#define SMEM_PROJ ((8192 + 64 + EPB * PRP) * 4)

// Scratch (device globals: allocation-free rule)
__device__ __align__(16) float g_x[(size_t)NN * H];
__device__ __align__(16) float g_p1[(size_t)NN * H];
__device__ __align__(16) float g_p2[(size_t)NN * H];
__device__ __align__(16) float g_agg[(size_t)NN * H];
__device__ float g_cnt[NN];
__device__ float g_sum[H];
__device__ unsigned g_maxb[H];

// ---------- packed f32x2 helpers ----------
__device__ __forceinline__ uint64_t pk2(float lo, float hi) {
    uint64_t r;
    asm("mov.b64 %0, {%1, %2};" : "=l"(r) : "r"(__float_as_uint(lo)), "r"(__float_as_uint(hi)));
    return r;
}
__device__ __forceinline__ uint64_t dup2(float a) {
    uint64_t r;
    asm("mov.b64 %0, {%1, %1};" : "=l"(r) : "r"(__float_as_uint(a)));
    return r;
}
__device__ __forceinline__ void fma2(uint64_t& acc, uint64_t w, uint64_t p) {
    asm("fma.rn.f32x2 %0, %1, %2, %0;" : "+l"(acc) : "l"(w), "l"(p));
}
__device__ __forceinline__ void unpk(uint64_t v, float& lo, float& hi) {
    unsigned a, b;
    asm("mov.b64 {%0, %1}, %2;" : "=r"(a), "=r"(b) : "l"(v));
    lo = __uint_as_float(a); hi = __uint_as_float(b);
}
__device__ __forceinline__ void redv4(float* p, float a, float b, float c, float d) {
    asm volatile("red.global.add.v4.f32 [%0], {%1, %2, %3, %4};"
                 :: "l"(p), "f"(a), "f"(b), "f"(c), "f"(d) : "memory");
}
__device__ __forceinline__ unsigned encf(float f) {
    unsigned u = __float_as_uint(f);
    return (u & 0x80000000u) ? ~u : (u | 0x80000000u);
}
__device__ __forceinline__ float decf(unsigned u) {
    return (u & 0x80000000u) ? __uint_as_float(u & 0x7FFFFFFFu) : __uint_as_float(~u);
}

// ---------- setup kernels ----------
__global__ void k_init() {
    int i = blockIdx.x * blockDim.x + threadIdx.x;
    int stride = gridDim.x * blockDim.x;
    for (int n = i; n < NN; n += stride) g_cnt[n] = 0.f;
    if (i < H) { g_sum[i] = 0.f; g_maxb[i] = 0u; }
}

__global__ void k_count(const int* __restrict__ edges) {
    int i = blockIdx.x * blockDim.x + threadIdx.x;
    int stride = gridDim.x * blockDim.x;
    for (int e = i; e < NE; e += stride)
        atomicAdd(&g_cnt[edges[2 * e + 1]], 1.0f);
}

__global__ void k_embed(const int* __restrict__ ti, const float* __restrict__ et) {
    int i = blockIdx.x * blockDim.x + threadIdx.x;
    int stride = gridDim.x * blockDim.x;
    for (int lin = i; lin < NN * 16; lin += stride) {
        int n = lin >> 4, q = lin & 15;
        ((float4*)g_x)[lin] = ((const float4*)et)[ti[n] * 16 + q];
    }
}

// ---------- per-node projection GEMM ----------
// P1[n] = x[n] @ W[0:64];  P2[n] = x[n] @ W[64:128] + b;  agg[n] = 0
__global__ __launch_bounds__(NT, 3) void k_proj(const float* __restrict__ W,
                                                const float* __restrict__ B) {
    extern __shared__ float sm[];
    float* Wsh = sm;             // 8192
    float* bsh = sm + 8192;      // 64
    float* xsh = sm + 8192 + 64; // 64 * PRP

    const int tid = threadIdx.x;
    for (int i = tid; i < 2048; i += NT) ((float4*)Wsh)[i] = ((const float4*)W)[i];
    if (tid < 16) ((float4*)bsh)[tid] = ((const float4*)B)[tid];
    __syncthreads();

    const int eg = tid >> 3, tg = tid & 7, j0 = tg << 3;
    const float* r0 = xsh + eg * PRP;
    const float* r1 = xsh + (eg + 32) * PRP;
    const float* w1p = Wsh + j0;          // rows 0..63
    const float* w2p = Wsh + 64 * 64 + j0; // rows 64..127

    const int ntiles = (NN + EPB - 1) / EPB;
    for (int tile = blockIdx.x; tile < ntiles; tile += gridDim.x) {
        const int base = tile * EPB;
        #pragma unroll
        for (int r = 0; r < 4; r++) {
            int lin = r * NT + tid;
            int nl = lin >> 4, q = lin & 15;
            int gn = base + nl;
            if (gn < NN)
                ((float4*)(xsh + nl * PRP))[q] = ((const float4*)g_x)[gn * 16 + q];
        }
        __syncthreads();

        // accumulators: [node0/1][P1: 4, P2: 4]
        uint64_t z = 0;
        uint64_t p1a0 = z, p1a1 = z, p1a2 = z, p1a3 = z;
        uint64_t p1b0 = z, p1b1 = z, p1b2 = z, p1b3 = z;
        uint64_t p2a0 = pk2(bsh[j0+0], bsh[j0+1]);
        uint64_t p2a1 = pk2(bsh[j0+2], bsh[j0+3]);
        uint64_t p2a2 = pk2(bsh[j0+4], bsh[j0+5]);
        uint64_t p2a3 = pk2(bsh[j0+6], bsh[j0+7]);
        uint64_t p2b0 = p2a0, p2b1 = p2a1, p2b2 = p2a2, p2b3 = p2a3;

        #pragma unroll 8
        for (int k = 0; k < 64; k++) {
            uint64_t x0 = dup2(r0[k]);
            uint64_t x1 = dup2(r1[k]);
            const ulonglong2* w1 = (const ulonglong2*)(w1p + k * 64);
            const ulonglong2* w2 = (const ulonglong2*)(w2p + k * 64);
            ulonglong2 wa = w1[0], wb = w1[1];
            ulonglong2 wc = w2[0], wd = w2[1];
            fma2(p1a0, wa.x, x0); fma2(p1a1, wa.y, x0);
            fma2(p1a2, wb.x, x0); fma2(p1a3, wb.y, x0);
            fma2(p1b0, wa.x, x1); fma2(p1b1, wa.y, x1);
            fma2(p1b2, wb.x, x1); fma2(p1b3, wb.y, x1);
            fma2(p2a0, wc.x, x0); fma2(p2a1, wc.y, x0);
            fma2(p2a2, wd.x, x0); fma2(p2a3, wd.y, x0);
            fma2(p2b0, wc.x, x1); fma2(p2b1, wc.y, x1);
            fma2(p2b2, wd.x, x1); fma2(p2b3, wd.y, x1);
        }

        float4 zero4 = make_float4(0.f, 0.f, 0.f, 0.f);
        {
            int gn = base + eg;
            if (gn < NN) {
                float v0,v1,v2,v3,v4,v5,v6,v7;
                unpk(p1a0,v0,v1); unpk(p1a1,v2,v3); unpk(p1a2,v4,v5); unpk(p1a3,v6,v7);
                float4* d1 = (float4*)(g_p1 + (size_t)gn * H + j0);
                d1[0] = make_float4(v0,v1,v2,v3); d1[1] = make_float4(v4,v5,v6,v7);
                unpk(p2a0,v0,v1); unpk(p2a1,v2,v3); unpk(p2a2,v4,v5); unpk(p2a3,v6,v7);
                float4* d2 = (float4*)(g_p2 + (size_t)gn * H + j0);
                d2[0] = make_float4(v0,v1,v2,v3); d2[1] = make_float4(v4,v5,v6,v7);
                float4* da = (float4*)(g_agg + (size_t)gn * H + j0);
                da[0] = zero4; da[1] = zero4;
            }
        }
        {
            int gn = base + eg + 32;
            if (gn < NN) {
                float v0,v1,v2,v3,v4,v5,v6,v7;
                unpk(p1b0,v0,v1); unpk(p1b1,v2,v3); unpk(p1b2,v4,v5); unpk(p1b3,v6,v7);
                float4* d1 = (float4*)(g_p1 + (size_t)gn * H + j0);
                d1[0] = make_float4(v0,v1,v2,v3); d1[1] = make_float4(v4,v5,v6,v7);
                unpk(p2b0,v0,v1); unpk(p2b1,v2,v3); unpk(p2b2,v4,v5); unpk(p2b3,v6,v7);
                float4* d2 = (float4*)(g_p2 + (size_t)gn * H + j0);
                d2[0] = make_float4(v0,v1,v2,v3); d2[1] = make_float4(v4,v5,v6,v7);
                float4* da = (float4*)(g_agg + (size_t)gn * H + j0);
                da[0] = zero4; da[1] = zero4;
            }
        }
        __syncthreads();
    }
}

// ---------- per-edge message: relu(P1[src] + P2[tgt]) red-> agg[tgt] ----------
__global__ __launch_bounds__(NT) void k_edge(const int* __restrict__ edges) {
    int idx = blockIdx.x * NT + threadIdx.x;   // NE*8 tasks exactly
    int e = idx >> 3, q = idx & 7;
    int2 ed = ((const int2*)edges)[e];
    const float4* p1 = (const float4*)(g_p1 + (size_t)ed.x * H) + q * 2;
    const float4* p2 = (const float4*)(g_p2 + (size_t)ed.y * H) + q * 2;
    float4 a0 = p1[0], b0 = p2[0];
    float4 a1 = p1[1], b1 = p2[1];
    float* dst = g_agg + (size_t)ed.y * H + q * 8;
    redv4(dst,     fmaxf(a0.x + b0.x, 0.f), fmaxf(a0.y + b0.y, 0.f),
                   fmaxf(a0.z + b0.z, 0.f), fmaxf(a0.w + b0.w, 0.f));
    redv4(dst + 4, fmaxf(a1.x + b1.x, 0.f), fmaxf(a1.y + b1.y, 0.f),
                   fmaxf(a1.z + b1.z, 0.f), fmaxf(a1.w + b1.w, 0.f));
}

// ---------- node update GEMM + residual + LayerNorm ----------
__global__ __launch_bounds__(NT, 3) void k_upd(const float* __restrict__ W,
                                               const float* __restrict__ B,
                                               const float* __restrict__ lng,
                                               const float* __restrict__ lnb) {
    extern __shared__ float sm[];
    float* Wsh  = sm;
    float* bsh  = sm + 8192;
    float* gsh  = sm + 8192 + 64;
    float* b2sh = gsh + 64;
    float* insh = sm + 8192 + 64 + 128;

    const int tid = threadIdx.x;
    for (int i = tid; i < 2048; i += NT) ((float4*)Wsh)[i] = ((const float4*)W)[i];
    if (tid < 16) ((float4*)bsh)[tid] = ((const float4*)B)[tid];
    if (tid >= 32 && tid < 48) ((float4*)gsh)[tid - 32]  = ((const float4*)lng)[tid - 32];
    if (tid >= 64 && tid < 80) ((float4*)b2sh)[tid - 64] = ((const float4*)lnb)[tid - 64];
    __syncthreads();

    const int eg = tid >> 3, tg = tid & 7, j0 = tg << 3;
    const float* r0 = insh + eg * RP;
    const float* r1 = insh + (eg + 32) * RP;
    const float* wp = Wsh + j0;

    const int ntiles = (NN + EPB - 1) / EPB;
    for (int tile = blockIdx.x; tile < ntiles; tile += gridDim.x) {
        const int base = tile * EPB;
        #pragma unroll
        for (int r = 0; r < 8; r++) {
            int lin = r * NT + tid;
            int nl = lin >> 5, q = lin & 31;
            int gn = base + nl;
            if (gn < NN) {
                float4 v;
                if (q < 16) {
                    v = ((const float4*)g_x)[gn * 16 + q];
                } else {
                    v = ((const float4*)g_agg)[gn * 16 + (q - 16)];
                    float ic = 1.0f / fmaxf(g_cnt[gn], 1.0f);
                    v.x *= ic; v.y *= ic; v.z *= ic; v.w *= ic;
                }
                ((float4*)(insh + nl * RP))[q] = v;
            }
        }
        __syncthreads();

        uint64_t a00 = pk2(bsh[j0+0], bsh[j0+1]);
        uint64_t a01 = pk2(bsh[j0+2], bsh[j0+3]);
        uint64_t a02 = pk2(bsh[j0+4], bsh[j0+5]);
        uint64_t a03 = pk2(bsh[j0+6], bsh[j0+7]);
        uint64_t a10 = a00, a11 = a01, a12 = a02, a13 = a03;

        #pragma unroll 16
        for (int k = 0; k < 128; k++) {
            uint64_t p0 = dup2(r0[k]);
            uint64_t p1 = dup2(r1[k]);
            const ulonglong2* w = (const ulonglong2*)(wp + k * 64);
            ulonglong2 wa = w[0];
            ulonglong2 wb = w[1];
            fma2(a00, wa.x, p0); fma2(a01, wa.y, p0);
            fma2(a02, wb.x, p0); fma2(a03, wb.y, p0);
            fma2(a10, wa.x, p1); fma2(a11, wa.y, p1);
            fma2(a12, wb.x, p1); fma2(a13, wb.y, p1);
        }

        {
            float h[8];
            { float lo, hi;
              unpk(a00, lo, hi); h[0] = fmaxf(lo,0.f) + r0[j0+0]; h[1] = fmaxf(hi,0.f) + r0[j0+1];
              unpk(a01, lo, hi); h[2] = fmaxf(lo,0.f) + r0[j0+2]; h[3] = fmaxf(hi,0.f) + r0[j0+3];
              unpk(a02, lo, hi); h[4] = fmaxf(lo,0.f) + r0[j0+4]; h[5] = fmaxf(hi,0.f) + r0[j0+5];
              unpk(a03, lo, hi); h[6] = fmaxf(lo,0.f) + r0[j0+6]; h[7] = fmaxf(hi,0.f) + r0[j0+7]; }
            float s1 = 0.f, s2 = 0.f;
            #pragma unroll
            for (int i = 0; i < 8; i++) { s1 += h[i]; s2 += h[i] * h[i]; }
            #pragma unroll
            for (int d = 1; d < 8; d <<= 1) {
                s1 += __shfl_xor_sync(0xFFFFFFFFu, s1, d);
                s2 += __shfl_xor_sync(0xFFFFFFFFu, s2, d);
            }
            float mu  = s1 * 0.015625f;
            float var = s2 * 0.015625f - mu * mu;
            float sc  = rsqrtf(fmaxf(var, 0.f) + 1e-5f);
            int gn0 = base + eg;
            if (gn0 < NN) {
                float o[8];
                #pragma unroll
                for (int i = 0; i < 8; i++) o[i] = (h[i] - mu) * sc * gsh[j0+i] + b2sh[j0+i];
                float4* dst = (float4*)(g_x + (size_t)gn0 * H + j0);
                dst[0] = make_float4(o[0], o[1], o[2], o[3]);
                dst[1] = make_float4(o[4], o[5], o[6], o[7]);
            }
        }
        {
            float h[8];
            { float lo, hi;
              unpk(a10, lo, hi); h[0] = fmaxf(lo,0.f) + r1[j0+0]; h[1] = fmaxf(hi,0.f) + r1[j0+1];
              unpk(a11, lo, hi); h[2] = fmaxf(lo,0.f) + r1[j0+2]; h[3] = fmaxf(hi,0.f) + r1[j0+3];
              unpk(a12, lo, hi); h[4] = fmaxf(lo,0.f) + r1[j0+4]; h[5] = fmaxf(hi,0.f) + r1[j0+5];
              unpk(a13, lo, hi); h[6] = fmaxf(lo,0.f) + r1[j0+6]; h[7] = fmaxf(hi,0.f) + r1[j0+7]; }
            float s1 = 0.f, s2 = 0.f;
            #pragma unroll
            for (int i = 0; i < 8; i++) { s1 += h[i]; s2 += h[i] * h[i]; }
            #pragma unroll
            for (int d = 1; d < 8; d <<= 1) {
                s1 += __shfl_xor_sync(0xFFFFFFFFu, s1, d);
                s2 += __shfl_xor_sync(0xFFFFFFFFu, s2, d);
            }
            float mu  = s1 * 0.015625f;
            float var = s2 * 0.015625f - mu * mu;
            float sc  = rsqrtf(fmaxf(var, 0.f) + 1e-5f);
            int gn1 = base + eg + 32;
            if (gn1 < NN) {
                float o[8];
                #pragma unroll
                for (int i = 0; i < 8; i++) o[i] = (h[i] - mu) * sc * gsh[j0+i] + b2sh[j0+i];
                float4* dst = (float4*)(g_x + (size_t)gn1 * H + j0);
                dst[0] = make_float4(o[0], o[1], o[2], o[3]);
                dst[1] = make_float4(o[4], o[5], o[6], o[7]);
            }
        }
        __syncthreads();
    }
}

// ---------- final mean/max over nodes ----------
__global__ void k_reduce() {
    __shared__ float rs[4][64];
    __shared__ float rm[4][64];
    int j = threadIdx.x & 63, g = threadIdx.x >> 6;
    float s = 0.f, m = -3.402823466e38f;
    for (int n = blockIdx.x * 4 + g; n < NN; n += gridDim.x * 4) {
        float v = g_x[(size_t)n * H + j];
        s += v; m = fmaxf(m, v);
    }
    rs[g][j] = s; rm[g][j] = m;
    __syncthreads();
    if (g == 0) {
        #pragma unroll
        for (int i = 1; i < 4; i++) { s += rs[i][j]; m = fmaxf(m, rm[i][j]); }
        atomicAdd(&g_sum[j], s);
        atomicMax(&g_maxb[j], encf(m));
    }
}

__global__ void k_final(float* out) {
    int t = threadIdx.x;
    if (t < 64) out[t] = g_sum[t] * (1.0f / NN);
    else        out[t] = decf(g_maxb[t - 64]);
}

// ---------- launch ----------
extern "C" void kernel_launch(void* const* d_in, const int* in_sizes, int n_in,
                              void* d_out, int out_size) {
    const int*   ti    = (const int*)d_in[0];
    const int*   edges = (const int*)d_in[1];
    const float* et    = (const float*)d_in[2];
    const float* msg_w = (const float*)d_in[3];
    const float* msg_b = (const float*)d_in[4];
    const float* upd_w = (const float*)d_in[5];
    const float* upd_b = (const float*)d_in[6];
    const float* lng   = (const float*)d_in[7];
    const float* lnb   = (const float*)d_in[8];
    float* out = (float*)d_out;

    cudaFuncSetAttribute(k_proj, cudaFuncAttributeMaxDynamicSharedMemorySize, SMEM_PROJ);
    cudaFuncSetAttribute(k_upd,  cudaFuncAttributeMaxDynamicSharedMemorySize, SMEM_UPD);

    k_init<<<392, 256>>>();
    k_embed<<<512, 256>>>(ti, et);
    k_count<<<512, 256>>>(edges);

    for (int l = 0; l < 3; l++) {
        k_proj<<<456, NT, SMEM_PROJ>>>(msg_w + l * 8192, msg_b + l * 64);
        k_edge<<<NE * 8 / NT, NT>>>(edges);
        k_upd<<<456, NT, SMEM_UPD>>>(upd_w + l * 8192, upd_b + l * 64,
                                     lng + l * 64, lnb + l * 64);
    }

    k_reduce<<<296, 256>>>();
    k_final<<<1, 128>>>(out);
}

// round 3
// speedup vs baseline: 5.9513x; 1.9740x over previous
#include <cuda_runtime.h>
#include <cstdint>

#define NN 100000
#define NE 800000
#define H  64
#define NT 256
#define TR 64                 // rows per GEMM tile
#define NTILES ((NN + TR - 1) / TR)
#define XP 68                 // proj x smem pitch (floats)
#define UP 132                // upd in smem pitch (floats)
#define SMEM_PROJ ((8192 + 64 + TR * XP) * 4)
#define SMEM_UPD  ((8192 + 64 + 128 + TR * UP) * 4)
#define NBLK 391              // scan blocks (391*256 >= NN)

// Scratch (device globals: allocation-free rule)
__device__ __align__(16) float g_x[(size_t)NN * H];
__device__ __align__(16) float g_p1[(size_t)NN * H];
__device__ __align__(16) float g_p2[(size_t)NN * H];
__device__ __align__(16) float g_agg[(size_t)NN * H];
__device__ int g_deg[NN];
__device__ int g_off[NN + 1];
__device__ int g_cur[NN];
__device__ int g_csr[NE];
__device__ int g_bsum[NBLK];
__device__ int g_boff[NBLK];
__device__ float g_sum[H];
__device__ unsigned g_maxb[H];

// ---------- packed f32x2 helpers ----------
__device__ __forceinline__ uint64_t pk2(float lo, float hi) {
    uint64_t r;
    asm("mov.b64 %0, {%1, %2};" : "=l"(r) : "r"(__float_as_uint(lo)), "r"(__float_as_uint(hi)));
    return r;
}
__device__ __forceinline__ uint64_t dup2(float a) {
    uint64_t r;
    asm("mov.b64 %0, {%1, %1};" : "=l"(r) : "r"(__float_as_uint(a)));
    return r;
}
__device__ __forceinline__ void fma2(uint64_t& acc, uint64_t w, uint64_t p) {
    asm("fma.rn.f32x2 %0, %1, %2, %0;" : "+l"(acc) : "l"(w), "l"(p));
}
__device__ __forceinline__ void unpk(uint64_t v, float& lo, float& hi) {
    unsigned a, b;
    asm("mov.b64 {%0, %1}, %2;" : "=r"(a), "=r"(b) : "l"(v));
    lo = __uint_as_float(a); hi = __uint_as_float(b);
}
__device__ __forceinline__ unsigned encf(float f) {
    unsigned u = __float_as_uint(f);
    return (u & 0x80000000u) ? ~u : (u | 0x80000000u);
}
__device__ __forceinline__ float decf(unsigned u) {
    return (u & 0x80000000u) ? __uint_as_float(u & 0x7FFFFFFFu) : __uint_as_float(~u);
}

// ---------- setup ----------
__global__ void k_init() {
    int i = blockIdx.x * blockDim.x + threadIdx.x;
    int stride = gridDim.x * blockDim.x;
    for (int n = i; n < NN; n += stride) g_deg[n] = 0;
    if (i < H) { g_sum[i] = 0.f; g_maxb[i] = 0u; }
}

__global__ void k_embed(const int* __restrict__ ti, const float* __restrict__ et) {
    int i = blockIdx.x * blockDim.x + threadIdx.x;
    int stride = gridDim.x * blockDim.x;
    for (int lin = i; lin < NN * 16; lin += stride) {
        int n = lin >> 4, q = lin & 15;
        ((float4*)g_x)[lin] = ((const float4*)et)[ti[n] * 16 + q];
    }
}

__global__ void k_hist(const int* __restrict__ edges) {
    int i = blockIdx.x * blockDim.x + threadIdx.x;
    int stride = gridDim.x * blockDim.x;
    for (int e = i; e < NE; e += stride)
        atomicAdd(&g_deg[((const int2*)edges)[e].y], 1);
}

// ---------- exclusive scan of g_deg -> g_off ----------
__global__ void k_scan1() {
    __shared__ int s[256];
    int t = threadIdx.x;
    int i = blockIdx.x * 256 + t;
    int v = (i < NN) ? g_deg[i] : 0;
    s[t] = v;
    __syncthreads();
    #pragma unroll
    for (int d = 1; d < 256; d <<= 1) {
        int tv = (t >= d) ? s[t - d] : 0;
        __syncthreads();
        s[t] += tv;
        __syncthreads();
    }
    if (i < NN) g_off[i] = s[t] - v;
    if (t == 255) g_bsum[blockIdx.x] = s[255];
}

__global__ void k_scan2() {
    __shared__ int s[512];
    int t = threadIdx.x;
    int v = (t < NBLK) ? g_bsum[t] : 0;
    s[t] = v;
    __syncthreads();
    #pragma unroll
    for (int d = 1; d < 512; d <<= 1) {
        int tv = (t >= d) ? s[t - d] : 0;
        __syncthreads();
        s[t] += tv;
        __syncthreads();
    }
    if (t < NBLK) g_boff[t] = s[t] - v;
}

__global__ void k_scan3() {
    int i = blockIdx.x * blockDim.x + threadIdx.x;
    if (i < NN) {
        int val = g_off[i] + g_boff[i >> 8];
        g_off[i] = val;
        g_cur[i] = val;
    }
    if (i == 0) g_off[NN] = NE;
}

__global__ void k_scatter(const int* __restrict__ edges) {
    int e = blockIdx.x * blockDim.x + threadIdx.x;
    if (e < NE) {
        int2 ed = ((const int2*)edges)[e];
        int pos = atomicAdd(&g_cur[ed.y], 1);
        g_csr[pos] = ed.x;
    }
}

// ---------- per-node projection: P1 = x@W[:64]; P2 = x@W[64:] + b ----------
__global__ __launch_bounds__(NT, 3) void k_proj(const float* __restrict__ W,
                                                const float* __restrict__ B) {
    extern __shared__ float sm[];
    float* Wsh = sm;              // 8192
    float* bsh = sm + 8192;       // 64
    float* xsh = sm + 8192 + 64;  // TR * XP

    const int tid = threadIdx.x;
    for (int i = tid; i < 2048; i += NT) ((float4*)Wsh)[i] = ((const float4*)W)[i];
    if (tid < 16) ((float4*)bsh)[tid] = ((const float4*)B)[tid];
    __syncthreads();

    const int cg = tid & 15;      // 16 col-groups x 4 cols
    const int rg = tid >> 4;      // 16 row-groups; rows rg + 16j

    for (int tile = blockIdx.x; tile < NTILES; tile += gridDim.x) {
        const int base = tile * TR;
        #pragma unroll
        for (int r = 0; r < 4; r++) {
            int lin = r * NT + tid;
            int nl = lin >> 4, q = lin & 15;
            int gn = base + nl;
            float4 v = make_float4(0.f, 0.f, 0.f, 0.f);
            if (gn < NN) v = ((const float4*)g_x)[gn * 16 + q];
            ((float4*)(xsh + nl * XP))[q] = v;
        }
        __syncthreads();

        uint64_t acc1[4][2], acc2[4][2];
        uint64_t b0 = pk2(bsh[cg * 4 + 0], bsh[cg * 4 + 1]);
        uint64_t b1 = pk2(bsh[cg * 4 + 2], bsh[cg * 4 + 3]);
        #pragma unroll
        for (int j = 0; j < 4; j++) {
            acc1[j][0] = 0; acc1[j][1] = 0;
            acc2[j][0] = b0; acc2[j][1] = b1;
        }

        #pragma unroll 4
        for (int k0 = 0; k0 < 64; k0 += 4) {
            float xr[4][4];
            #pragma unroll
            for (int j = 0; j < 4; j++) {
                float4 t = *(const float4*)(xsh + (rg + 16 * j) * XP + k0);
                xr[j][0] = t.x; xr[j][1] = t.y; xr[j][2] = t.z; xr[j][3] = t.w;
            }
            #pragma unroll
            for (int i = 0; i < 4; i++) {
                ulonglong2 w1 = *(const ulonglong2*)(Wsh + (k0 + i) * 64 + cg * 4);
                ulonglong2 w2 = *(const ulonglong2*)(Wsh + (64 + k0 + i) * 64 + cg * 4);
                #pragma unroll
                for (int j = 0; j < 4; j++) {
                    uint64_t p = dup2(xr[j][i]);
                    fma2(acc1[j][0], w1.x, p); fma2(acc1[j][1], w1.y, p);
                    fma2(acc2[j][0], w2.x, p); fma2(acc2[j][1], w2.y, p);
                }
            }
        }

        #pragma unroll
        for (int j = 0; j < 4; j++) {
            int gn = base + rg + 16 * j;
            if (gn < NN) {
                float v0, v1, v2, v3;
                unpk(acc1[j][0], v0, v1); unpk(acc1[j][1], v2, v3);
                *(float4*)(g_p1 + (size_t)gn * H + cg * 4) = make_float4(v0, v1, v2, v3);
                unpk(acc2[j][0], v0, v1); unpk(acc2[j][1], v2, v3);
                *(float4*)(g_p2 + (size_t)gn * H + cg * 4) = make_float4(v0, v1, v2, v3);
            }
        }
        __syncthreads();
    }
}

// ---------- CSR edge pass: agg[n] = sum_{src in N(n)} relu(P1[src] + P2[n]) ----------
__global__ __launch_bounds__(NT) void k_edge() {
    int idx = blockIdx.x * NT + threadIdx.x;  // NN*8 tasks exactly
    int n = idx >> 3, q = idx & 7;
    int s0 = g_off[n], s1 = g_off[n + 1];
    const float4* p2 = (const float4*)(g_p2 + (size_t)n * H) + q * 2;
    float4 b0 = p2[0], b1 = p2[1];
    float a[8] = {0.f, 0.f, 0.f, 0.f, 0.f, 0.f, 0.f, 0.f};
    for (int i = s0; i < s1; i++) {
        int src = g_csr[i];
        const float4* p1 = (const float4*)(g_p1 + (size_t)src * H) + q * 2;
        float4 c0 = p1[0], c1 = p1[1];
        a[0] += fmaxf(c0.x + b0.x, 0.f); a[1] += fmaxf(c0.y + b0.y, 0.f);
        a[2] += fmaxf(c0.z + b0.z, 0.f); a[3] += fmaxf(c0.w + b0.w, 0.f);
        a[4] += fmaxf(c1.x + b1.x, 0.f); a[5] += fmaxf(c1.y + b1.y, 0.f);
        a[6] += fmaxf(c1.z + b1.z, 0.f); a[7] += fmaxf(c1.w + b1.w, 0.f);
    }
    float4* dst = (float4*)(g_agg + (size_t)n * H + q * 8);
    dst[0] = make_float4(a[0], a[1], a[2], a[3]);
    dst[1] = make_float4(a[4], a[5], a[6], a[7]);
}

// ---------- node update GEMM + residual + LayerNorm ----------
__global__ __launch_bounds__(NT, 3) void k_upd(const float* __restrict__ W,
                                               const float* __restrict__ B,
                                               const float* __restrict__ lng,
                                               const float* __restrict__ lnb) {
    extern __shared__ float sm[];
    float* Wsh  = sm;
    float* bsh  = sm + 8192;
    float* gsh  = sm + 8192 + 64;
    float* b2sh = gsh + 64;
    float* insh = sm + 8192 + 64 + 128;   // TR * UP

    const int tid = threadIdx.x;
    for (int i = tid; i < 2048; i += NT) ((float4*)Wsh)[i] = ((const float4*)W)[i];
    if (tid < 16) ((float4*)bsh)[tid] = ((const float4*)B)[tid];
    if (tid >= 32 && tid < 48) ((float4*)gsh)[tid - 32]  = ((const float4*)lng)[tid - 32];
    if (tid >= 64 && tid < 80) ((float4*)b2sh)[tid - 64] = ((const float4*)lnb)[tid - 64];
    __syncthreads();

    const int cg = tid & 15;
    const int rg = tid >> 4;

    for (int tile = blockIdx.x; tile < NTILES; tile += gridDim.x) {
        const int base = tile * TR;
        #pragma unroll
        for (int r = 0; r < 8; r++) {
            int lin = r * NT + tid;
            int nl = lin >> 5, q = lin & 31;
            int gn = base + nl;
            float4 v = make_float4(0.f, 0.f, 0.f, 0.f);
            if (gn < NN) {
                if (q < 16) {
                    v = ((const float4*)g_x)[gn * 16 + q];
                } else {
                    v = ((const float4*)g_agg)[gn * 16 + (q - 16)];
                    float ic = 1.0f / fmaxf((float)g_deg[gn], 1.0f);
                    v.x *= ic; v.y *= ic; v.z *= ic; v.w *= ic;
                }
            }
            ((float4*)(insh + nl * UP))[q] = v;
        }
        __syncthreads();

        uint64_t acc[4][2];
        uint64_t b0 = pk2(bsh[cg * 4 + 0], bsh[cg * 4 + 1]);
        uint64_t b1 = pk2(bsh[cg * 4 + 2], bsh[cg * 4 + 3]);
        #pragma unroll
        for (int j = 0; j < 4; j++) { acc[j][0] = b0; acc[j][1] = b1; }

        #pragma unroll 4
        for (int k0 = 0; k0 < 128; k0 += 4) {
            float xr[4][4];
            #pragma unroll
            for (int j = 0; j < 4; j++) {
                float4 t = *(const float4*)(insh + (rg + 16 * j) * UP + k0);
                xr[j][0] = t.x; xr[j][1] = t.y; xr[j][2] = t.z; xr[j][3] = t.w;
            }
            #pragma unroll
            for (int i = 0; i < 4; i++) {
                ulonglong2 w = *(const ulonglong2*)(Wsh + (k0 + i) * 64 + cg * 4);
                #pragma unroll
                for (int j = 0; j < 4; j++) {
                    uint64_t p = dup2(xr[j][i]);
                    fma2(acc[j][0], w.x, p); fma2(acc[j][1], w.y, p);
                }
            }
        }

        // epilogue: relu + residual + LN (row sums across 16-lane half-warp groups)
        #pragma unroll
        for (int j = 0; j < 4; j++) {
            int row = rg + 16 * j;
            int gn = base + row;
            float u0, u1, u2, u3;
            unpk(acc[j][0], u0, u1); unpk(acc[j][1], u2, u3);
            const float* xo = insh + row * UP + cg * 4;
            float h0 = fmaxf(u0, 0.f) + xo[0];
            float h1 = fmaxf(u1, 0.f) + xo[1];
            float h2 = fmaxf(u2, 0.f) + xo[2];
            float h3 = fmaxf(u3, 0.f) + xo[3];
            float s1 = h0 + h1 + h2 + h3;
            float s2 = h0 * h0 + h1 * h1 + h2 * h2 + h3 * h3;
            #pragma unroll
            for (int d = 1; d < 16; d <<= 1) {
                s1 += __shfl_xor_sync(0xFFFFFFFFu, s1, d);
                s2 += __shfl_xor_sync(0xFFFFFFFFu, s2, d);
            }
            float mu  = s1 * 0.015625f;
            float var = s2 * 0.015625f - mu * mu;
            float sc  = rsqrtf(fmaxf(var, 0.f) + 1e-5f);
            if (gn < NN) {
                float o0 = (h0 - mu) * sc * gsh[cg * 4 + 0] + b2sh[cg * 4 + 0];
                float o1 = (h1 - mu) * sc * gsh[cg * 4 + 1] + b2sh[cg * 4 + 1];
                float o2 = (h2 - mu) * sc * gsh[cg * 4 + 2] + b2sh[cg * 4 + 2];
                float o3 = (h3 - mu) * sc * gsh[cg * 4 + 3] + b2sh[cg * 4 + 3];
                *(float4*)(g_x + (size_t)gn * H + cg * 4) = make_float4(o0, o1, o2, o3);
            }
        }
        __syncthreads();
    }
}

// ---------- final mean/max over nodes ----------
__global__ void k_reduce() {
    __shared__ float rs[4][64];
    __shared__ float rm[4][64];
    int j = threadIdx.x & 63, g = threadIdx.x >> 6;
    float s = 0.f, m = -3.402823466e38f;
    for (int n = blockIdx.x * 4 + g; n < NN; n += gridDim.x * 4) {
        float v = g_x[(size_t)n * H + j];
        s += v; m = fmaxf(m, v);
    }
    rs[g][j] = s; rm[g][j] = m;
    __syncthreads();
    if (g == 0) {
        #pragma unroll
        for (int i = 1; i < 4; i++) { s += rs[i][j]; m = fmaxf(m, rm[i][j]); }
        atomicAdd(&g_sum[j], s);
        atomicMax(&g_maxb[j], encf(m));
    }
}

__global__ void k_final(float* out) {
    int t = threadIdx.x;
    if (t < 64) out[t] = g_sum[t] * (1.0f / NN);
    else        out[t] = decf(g_maxb[t - 64]);
}

// ---------- launch ----------
extern "C" void kernel_launch(void* const* d_in, const int* in_sizes, int n_in,
                              void* d_out, int out_size) {
    const int*   ti    = (const int*)d_in[0];
    const int*   edges = (const int*)d_in[1];
    const float* et    = (const float*)d_in[2];
    const float* msg_w = (const float*)d_in[3];
    const float* msg_b = (const float*)d_in[4];
    const float* upd_w = (const float*)d_in[5];
    const float* upd_b = (const float*)d_in[6];
    const float* lng   = (const float*)d_in[7];
    const float* lnb   = (const float*)d_in[8];
    float* out = (float*)d_out;

    cudaFuncSetAttribute(k_proj, cudaFuncAttributeMaxDynamicSharedMemorySize, SMEM_PROJ);
    cudaFuncSetAttribute(k_upd,  cudaFuncAttributeMaxDynamicSharedMemorySize, SMEM_UPD);

    k_init<<<392, 256>>>();
    k_embed<<<512, 256>>>(ti, et);
    k_hist<<<512, 256>>>(edges);
    k_scan1<<<NBLK, 256>>>();
    k_scan2<<<1, 512>>>();
    k_scan3<<<392, 256>>>();
    k_scatter<<<(NE + 255) / 256, 256>>>(edges);

    for (int l = 0; l < 3; l++) {
        k_proj<<<444, NT, SMEM_PROJ>>>(msg_w + l * 8192, msg_b + l * 64);
        k_edge<<<NN * 8 / NT, NT>>>();
        k_upd<<<444, NT, SMEM_UPD>>>(upd_w + l * 8192, upd_b + l * 64,
                                     lng + l * 64, lnb + l * 64);
    }

    k_reduce<<<296, 256>>>();
    k_final<<<1, 128>>>(out);
}